// round 15
// baseline (speedup 1.0000x reference)
#include <cuda_runtime.h>
#include <math.h>

// Problem constants
#define TN    8192
#define LOGN  13
#define HIDN  64
#define BN    8
#define CINN  32
#define COUTN 32
#define CTOTN 1024   // COUT*CIN
#define NFREQ 4097   // rfft bins
#define FSTR  4104   // padded row stride (complex), mult of 8

// padded smem index for FFT: one float2 of pad every 16
#define PADI(i) ((i) + ((i) >> 4))
#define SBUF 8704                       // padded float2 count for 8192
#define FFT_SM (SBUF * 8)               // 69632 bytes, single buffer

typedef unsigned long long u64;

// ---------------- device scratch ------------------------------------------------
__device__ float2 d_tw[TN];                        // exp(-2*pi*i*k/N)
__device__ float  d_h2t[HIDN * TN];                // h2 transposed: [j][t]
__device__ float2 d_G[HIDN * FSTR];                // rfft(h2)
__device__ float2 d_Xf[(size_t)(BN * CINN) * FSTR];   // rfft(x)
__device__ float2 d_Yf[(size_t)(BN * COUTN) * FSTR];  // result spectra (half)

// ---------------- complex helpers -----------------------------------------------
__device__ __forceinline__ float2 cadd(float2 a, float2 b) { return make_float2(a.x + b.x, a.y + b.y); }
__device__ __forceinline__ float2 csub(float2 a, float2 b) { return make_float2(a.x - b.x, a.y - b.y); }
__device__ __forceinline__ float2 cmul(float2 a, float2 b) {
    return make_float2(a.x * b.x - a.y * b.y, a.x * b.y + a.y * b.x);
}

// ---------------- twiddle table -------------------------------------------------
__global__ void k_twiddle() {
    int k = blockIdx.x * blockDim.x + threadIdx.x;
    if (k < TN) {
        float s, c;
        sincospif(-2.0f * (float)k / (float)TN, &s, &c);
        d_tw[k] = make_float2(c, s);
    }
}

// ---------------- MLP -----------------------------------------------------------
__global__ void k_mlp(const float* __restrict__ w1, const float* __restrict__ b1,
                      const float* __restrict__ w2, const float* __restrict__ b2) {
    __shared__ float h1[4][HIDN];
    int g = threadIdx.x >> 6;
    int j = threadIdx.x & 63;
    int t = blockIdx.x * 4 + g;
    float pos = (float)t * (1.0f / (float)(TN - 1));
    float z = pos * w1[j] + b1[j];
    h1[g][j] = 0.5f * z * (1.0f + erff(z * 0.7071067811865476f));
    __syncthreads();
    float acc = b2[j];
#pragma unroll
    for (int k = 0; k < HIDN; k++) acc += h1[g][k] * w2[k * HIDN + j];
    float h2 = 0.5f * acc * (1.0f + erff(acc * 0.7071067811865476f));
    d_h2t[j * TN + t] = h2;
}

// ---------------- radix-8 Stockham FFT, in-place smem, 512 threads --------------
__device__ __forceinline__ void dft8(const float2* v, float2* y) {
    const float S = 0.70710678118654752f;
    float2 a0 = cadd(v[0], v[4]), b0 = csub(v[0], v[4]);
    float2 a1 = cadd(v[1], v[5]), b1 = csub(v[1], v[5]);
    float2 a2 = cadd(v[2], v[6]), b2 = csub(v[2], v[6]);
    float2 a3 = cadd(v[3], v[7]), b3 = csub(v[3], v[7]);
    float2 c0 = cadd(a0, a2), c1 = csub(a0, a2);
    float2 c2 = cadd(a1, a3), c3 = csub(a1, a3);
    y[0] = cadd(c0, c2); y[4] = csub(c0, c2);
    float2 mc3 = make_float2(c3.y, -c3.x);
    y[2] = cadd(c1, mc3); y[6] = csub(c1, mc3);
    b1 = make_float2(S * (b1.x + b1.y), S * (b1.y - b1.x));
    b2 = make_float2(b2.y, -b2.x);
    b3 = make_float2(S * (b3.y - b3.x), -S * (b3.x + b3.y));
    float2 d0 = cadd(b0, b2), d1 = csub(b0, b2);
    float2 d2 = cadd(b1, b3), d3 = csub(b1, b3);
    y[1] = cadd(d0, d2); y[5] = csub(d0, d2);
    float2 md3 = make_float2(d3.y, -d3.x);
    y[3] = cadd(d1, md3); y[7] = csub(d1, md3);
}

template <int LS>
__device__ __forceinline__ void pass8ip(float2* A, int t) {
    float2 v[2][8];
#pragma unroll
    for (int u = 0; u < 2; u++) {
        int i = t + u * 512;
        int j = i & (LS - 1);
#pragma unroll
        for (int q = 0; q < 8; q++) v[u][q] = A[PADI(i + q * 1024)];
        if (LS > 1) {
#pragma unroll
            for (int q = 1; q < 8; q++)
                v[u][q] = cmul(v[u][q], d_tw[j * q * (1024 / LS)]);
        }
    }
    __syncthreads();
#pragma unroll
    for (int u = 0; u < 2; u++) {
        int i = t + u * 512;
        int j = i & (LS - 1);
        int base = ((i & ~(LS - 1)) << 3) | j;
        float2 y[8];
        dft8(v[u], y);
#pragma unroll
        for (int q = 0; q < 8; q++) A[PADI(base + q * LS)] = y[q];
    }
    __syncthreads();
}

__device__ __forceinline__ void fft_passes_ip(float2* A, int t) {
    pass8ip<1>(A, t);
    pass8ip<8>(A, t);
    pass8ip<64>(A, t);
    pass8ip<512>(A, t);
#pragma unroll
    for (int u = 0; u < 8; u++) {
        int i = t + u * 512;
        float2 a = A[PADI(i)];
        float2 b = cmul(A[PADI(i + 4096)], d_tw[i]);
        A[PADI(i)]        = cadd(a, b);
        A[PADI(i + 4096)] = csub(a, b);
    }
    __syncthreads();
}

// ---------------- forward FFTs: G rows (blocks 0..31) + x rows (32..159) --------
__global__ void __launch_bounds__(512, 2)
k_fft_fwd(const float* __restrict__ x) {
    extern __shared__ float2 A[];
    int t = threadIdx.x;
    const float* ra;
    float2* oa;
    if (blockIdx.x < HIDN / 2) {
        ra = d_h2t + (size_t)(2 * blockIdx.x) * TN;
        oa = d_G   + (size_t)(2 * blockIdx.x) * FSTR;
    } else {
        int bb = blockIdx.x - HIDN / 2;
        ra = x    + (size_t)(2 * bb) * TN;
        oa = d_Xf + (size_t)(2 * bb) * FSTR;
    }
    const float* rb = ra + TN;
#pragma unroll
    for (int u = 0; u < 16; u++) {
        int idx = t + u * 512;
        A[PADI(idx)] = make_float2(ra[idx], rb[idx]);
    }
    __syncthreads();
    fft_passes_ip(A, t);
#pragma unroll
    for (int u = 0; u < 8; u++) {
        int f = t + u * 512;
        float2 uu = A[PADI(f)];
        float2 vv = A[PADI((TN - f) & (TN - 1))];
        float vx = vv.x, vy = -vv.y;
        oa[f] = make_float2(0.5f * (uu.x + vx), 0.5f * (uu.y + vy));
        float wx = uu.x - vx, wyv = uu.y - vy;
        oa[FSTR + f] = make_float2(0.5f * wyv, -0.5f * wx);
    }
    if (t == 0) {
        float2 uu = A[PADI(TN / 2)];
        oa[TN / 2]        = make_float2(uu.x, 0.f);
        oa[FSTR + TN / 2] = make_float2(uu.y, 0.f);
    }
}

// ---------------- fused Hf-GEMM + contraction (f-tile 64) -----------------------
// Block: c-tile 128 (= 4 o x 32 i), f-tile 64. Grid (65 f, 8 o-groups).
// Phase1: thread = 4c x 8f, M[c][f] = sum_j w3[j][c]*G[j][f]; per j:
//   2 LDS.128 (dup-w) + 4 LDS.128 (G, group-stride 10 u64 = conflict-free) + 32 FFMA2.
// Phase2: Ms[128][66] f2 + Xs[256][18] f2, 4 halves of 16 f, thread = (o,b,2f).
#define GSTR 80   // u64 per j-row of Gs (8 groups x 10)
#define HFC_SM (64 * 128 * 8 + 64 * GSTR * 8)   // 106496

__global__ void __launch_bounds__(256, 2)
k_hfc(const float* __restrict__ w3, const float* __restrict__ b3) {
    extern __shared__ __align__(16) char smraw[];
    u64* w3d = (u64*)smraw;              // [64 j][128 c] duplicated {w,w}
    u64* Gs  = (u64*)smraw + 64 * 128;   // [64 j][8 tf-groups x 10]
    int f0 = blockIdx.x * 64;
    int c0 = blockIdx.y * 128;
    int tid = threadIdx.x;

    // ---- stage w3 (duplicated) ----
    for (int m = tid; m < 64 * 32; m += 256) {
        int j = m >> 5, cq = m & 31;
        float4 w = *(const float4*)(w3 + (size_t)j * CTOTN + c0 + cq * 4);
        u64 d0, d1, d2, d3;
        asm("mov.b64 %0, {%1, %1};" : "=l"(d0) : "f"(w.x));
        asm("mov.b64 %0, {%1, %1};" : "=l"(d1) : "f"(w.y));
        asm("mov.b64 %0, {%1, %1};" : "=l"(d2) : "f"(w.z));
        asm("mov.b64 %0, {%1, %1};" : "=l"(d3) : "f"(w.w));
        u64* dst = w3d + j * 128 + cq * 4;
        dst[0] = d0; dst[1] = d1; dst[2] = d2; dst[3] = d3;
    }
    // ---- stage G: pos = j*80 + (f&7)*10 + (f>>3) ----
    for (int m = tid; m < 64 * 64; m += 256) {
        int j = m >> 6, f = m & 63;
        float2 g = (f0 + f < NFREQ) ? d_G[(size_t)j * FSTR + f0 + f]
                                    : make_float2(0.f, 0.f);
        u64 gv;
        asm("mov.b64 %0, {%1, %2};" : "=l"(gv) : "f"(g.x), "f"(g.y));
        Gs[j * GSTR + (f & 7) * 10 + (f >> 3)] = gv;
    }
    __syncthreads();

    // ---- phase 1: thread = 4c x 8f (f = f0 + tf + 8k) ----
    int tc = tid >> 3;   // 0..31
    int tf = tid & 7;    // 0..7
    const u64* wrow = w3d + tc * 4;
    const u64* grow = Gs + tf * 10;
    u64 acc[4][8];
#pragma unroll
    for (int cc = 0; cc < 4; cc++)
#pragma unroll
        for (int k = 0; k < 8; k++) acc[cc][k] = 0ull;

#pragma unroll 1
    for (int j = 0; j < 64; j++) {
        ulonglong2 w01 = *(const ulonglong2*)(wrow + j * 128);
        ulonglong2 w23 = *(const ulonglong2*)(wrow + j * 128 + 2);
        ulonglong2 gA = *(const ulonglong2*)(grow + j * GSTR);
        ulonglong2 gB = *(const ulonglong2*)(grow + j * GSTR + 2);
        ulonglong2 gC = *(const ulonglong2*)(grow + j * GSTR + 4);
        ulonglong2 gD = *(const ulonglong2*)(grow + j * GSTR + 6);
        u64 w[4] = {w01.x, w01.y, w23.x, w23.y};
        u64 g[8] = {gA.x, gA.y, gB.x, gB.y, gC.x, gC.y, gD.x, gD.y};
#pragma unroll
        for (int cc = 0; cc < 4; cc++)
#pragma unroll
            for (int k = 0; k < 8; k++)
                asm("fma.rn.f32x2 %0, %1, %2, %0;"
                    : "+l"(acc[cc][k]) : "l"(w[cc]), "l"(g[k]));
    }
    __syncthreads();   // phase-1 smem reads complete; safe to overwrite

    // ---- handoff: regs -> Ms [128 r][66 f2] ----
    float2* Ms = (float2*)smraw;               // 67584 bytes
    float2* Xs = (float2*)(smraw + 67584);     // [256 r][18 f2] = 36864
#pragma unroll
    for (int cc = 0; cc < 4; cc++) {
        int r = tc * 4 + cc;
        float dc = (f0 == 0 && tf == 0) ? (float)TN * b3[c0 + r] : 0.f;
#pragma unroll
        for (int k = 0; k < 8; k++) {
            float2 v;
            asm("mov.b64 {%0, %1}, %2;" : "=f"(v.x), "=f"(v.y) : "l"(acc[cc][k]));
            if (k == 0) v.x += dc;
            Ms[r * 66 + tf + 8 * k] = v;
        }
    }
    // ---- stage X half h=0 (16 complex = 8 float4) ----
    {
        const float2* xr = d_Xf + (size_t)tid * FSTR + f0;
        float2* xd = Xs + tid * 18;
        if (f0 + 16 <= NFREQ) {
            const float4* s4 = (const float4*)xr;
            float4* d4 = (float4*)xd;
#pragma unroll
            for (int q = 0; q < 8; q++) d4[q] = s4[q];
        } else {
#pragma unroll
            for (int f = 0; f < 16; f++)
                xd[f] = (f0 + f < NFREQ) ? xr[f] : make_float2(0.f, 0.f);
        }
    }
    __syncthreads();

    // ---- phase 2: 4 halves of 16 f; thread = (o, b, 2f) ----
    int o  = tid >> 6;
    int b  = (tid >> 3) & 7;
    int fq = tid & 7;
    int og = blockIdx.y * 4 + o;
#pragma unroll 1
    for (int h = 0; h < 4; h++) {
        if (h > 0) {
            __syncthreads();    // previous half's reads done
            int fb = f0 + h * 16;
            const float2* xr = d_Xf + (size_t)tid * FSTR + fb;
            float2* xd = Xs + tid * 18;
            if (fb + 16 <= NFREQ) {
                const float4* s4 = (const float4*)xr;
                float4* d4 = (float4*)xd;
#pragma unroll
                for (int q = 0; q < 8; q++) d4[q] = s4[q];
            } else {
#pragma unroll
                for (int f = 0; f < 16; f++)
                    xd[f] = (fb + f < NFREQ) ? xr[f] : make_float2(0.f, 0.f);
            }
            __syncthreads();
        }
        float2 a0 = make_float2(0.f, 0.f), a1 = make_float2(0.f, 0.f);
        const float2* mrow = Ms + (o * 32) * 66 + h * 16 + fq * 2;
        const float2* xrow = Xs + (b * 32) * 18 + fq * 2;
#pragma unroll 4
        for (int i = 0; i < 32; i++) {
            float4 xv = *(const float4*)(xrow + i * 18);
            float4 mv = *(const float4*)(mrow + i * 66);
            a0.x += xv.x * mv.x - xv.y * mv.y;
            a0.y += xv.x * mv.y + xv.y * mv.x;
            a1.x += xv.z * mv.z - xv.w * mv.w;
            a1.y += xv.z * mv.w + xv.w * mv.z;
        }
        int f = f0 + h * 16 + fq * 2;
        float2* yr = d_Yf + (size_t)(b * COUTN + og) * FSTR + f;
        if (f < NFREQ)     yr[0] = a0;
        if (f + 1 < NFREQ) yr[1] = a1;
    }
}

// ---------------- packed inverse FFT via conj(forward(conj)) --------------------
__global__ void __launch_bounds__(512, 2)
k_fft_inv(float* __restrict__ out, const float* __restrict__ bias) {
    extern __shared__ float2 A[];
    int t = threadIdx.x;
    int b = blockIdx.x >> 4, q = blockIdx.x & 15;
    int oc = 2 * q;
    const float2* ra = d_Yf + (size_t)(b * COUTN + oc) * FSTR;
    const float2* rb = ra + FSTR;
#pragma unroll
    for (int u = 0; u < 8; u++) {
        int f = t + u * 512;
        float2 Ya = ra[f], Yb = rb[f];
        A[PADI(f)] = make_float2(Ya.x - Yb.y, -(Ya.y + Yb.x));
        if (f > 0)
            A[PADI(TN - f)] = make_float2(Ya.x + Yb.y, Ya.y - Yb.x);
    }
    if (t == 0) {
        float2 Ya = ra[TN / 2], Yb = rb[TN / 2];
        A[PADI(TN / 2)] = make_float2(Ya.x - Yb.y, -(Ya.y + Yb.x));
    }
    __syncthreads();
    fft_passes_ip(A, t);
    const float sc = 1.0f / (float)TN;
    float ba = bias[oc], bb = bias[oc + 1];
    float* pa = out + (size_t)(b * COUTN + oc) * TN;
    float* pb = pa + TN;
#pragma unroll
    for (int u = 0; u < 16; u++) {
        int i = t + u * 512;
        float2 v = A[PADI(i)];
        pa[i] =  v.x * sc + ba;
        pb[i] = -v.y * sc + bb;
    }
}

// ---------------- launch --------------------------------------------------------
extern "C" void kernel_launch(void* const* d_in, const int* in_sizes, int n_in,
                              void* d_out, int out_size) {
    const float* x    = (const float*)d_in[0];
    const float* w1   = (const float*)d_in[1];
    const float* b1   = (const float*)d_in[2];
    const float* w2   = (const float*)d_in[3];
    const float* b2   = (const float*)d_in[4];
    const float* w3   = (const float*)d_in[5];
    const float* b3   = (const float*)d_in[6];
    const float* bias = (const float*)d_in[7];
    float* out = (float*)d_out;

    cudaFuncSetAttribute(k_fft_fwd, cudaFuncAttributeMaxDynamicSharedMemorySize, FFT_SM);
    cudaFuncSetAttribute(k_fft_inv, cudaFuncAttributeMaxDynamicSharedMemorySize, FFT_SM);
    cudaFuncSetAttribute(k_hfc,     cudaFuncAttributeMaxDynamicSharedMemorySize, HFC_SM);

    k_twiddle<<<32, 256>>>();
    k_mlp<<<TN / 4, 256>>>(w1, b1, w2, b2);
    k_fft_fwd<<<HIDN / 2 + BN * CINN / 2, 512, FFT_SM>>>(x);
    k_hfc<<<dim3(65, 8), 256, HFC_SM>>>(w3, b3);
    k_fft_inv<<<BN * COUTN / 2, 512, FFT_SM>>>(out, bias);
}

// round 16
// speedup vs baseline: 1.6713x; 1.6713x over previous
#include <cuda_runtime.h>
#include <math.h>

// Problem constants
#define TN    8192
#define LOGN  13
#define HIDN  64
#define BN    8
#define CINN  32
#define COUTN 32
#define CTOTN 1024   // COUT*CIN
#define NFREQ 4097   // rfft bins
#define FSTR  4104   // padded row stride (complex), mult of 8

// padded smem index: one float2 of pad every 16 (conflict-free phases)
#define PADI(i) ((i) + ((i) >> 4))
#define SBUF 8704

typedef unsigned long long u64;

// ---------------- device scratch ------------------------------------------------
__device__ float2 d_tw[TN];                        // exp(-2*pi*i*k/N)
__device__ float  d_h2t[HIDN * TN];                // h2 transposed: [j][t]
__device__ float2 d_G[HIDN * FSTR];                // rfft(h2)
__device__ float2 d_Xf[(size_t)(BN * CINN) * FSTR];   // rfft(x)
__device__ float2 d_Yf[(size_t)(BN * COUTN) * FSTR];  // result spectra (half)

// ---------------- complex helpers -----------------------------------------------
__device__ __forceinline__ float2 cadd(float2 a, float2 b) { return make_float2(a.x + b.x, a.y + b.y); }
__device__ __forceinline__ float2 csub(float2 a, float2 b) { return make_float2(a.x - b.x, a.y - b.y); }
__device__ __forceinline__ float2 cmul(float2 a, float2 b) {
    return make_float2(a.x * b.x - a.y * b.y, a.x * b.y + a.y * b.x);
}

// ---------------- twiddle table -------------------------------------------------
__global__ void k_twiddle() {
    int k = blockIdx.x * blockDim.x + threadIdx.x;
    if (k < TN) {
        float s, c;
        sincospif(-2.0f * (float)k / (float)TN, &s, &c);
        d_tw[k] = make_float2(c, s);
    }
}

// ---------------- MLP -----------------------------------------------------------
__global__ void k_mlp(const float* __restrict__ w1, const float* __restrict__ b1,
                      const float* __restrict__ w2, const float* __restrict__ b2) {
    __shared__ float h1[4][HIDN];
    int g = threadIdx.x >> 6;
    int j = threadIdx.x & 63;
    int t = blockIdx.x * 4 + g;
    float pos = (float)t * (1.0f / (float)(TN - 1));
    float z = pos * w1[j] + b1[j];
    h1[g][j] = 0.5f * z * (1.0f + erff(z * 0.7071067811865476f));
    __syncthreads();
    float acc = b2[j];
#pragma unroll
    for (int k = 0; k < HIDN; k++) acc += h1[g][k] * w2[k * HIDN + j];
    float h2 = 0.5f * acc * (1.0f + erff(acc * 0.7071067811865476f));
    d_h2t[j * TN + t] = h2;
}

// ---------------- radix-8 Stockham FFT (8192 pts, 1024 threads, ping-pong) ------
__device__ __forceinline__ void dft8(const float2* v, float2* y) {
    const float S = 0.70710678118654752f;
    float2 a0 = cadd(v[0], v[4]), b0 = csub(v[0], v[4]);
    float2 a1 = cadd(v[1], v[5]), b1 = csub(v[1], v[5]);
    float2 a2 = cadd(v[2], v[6]), b2 = csub(v[2], v[6]);
    float2 a3 = cadd(v[3], v[7]), b3 = csub(v[3], v[7]);
    float2 c0 = cadd(a0, a2), c1 = csub(a0, a2);
    float2 c2 = cadd(a1, a3), c3 = csub(a1, a3);
    y[0] = cadd(c0, c2); y[4] = csub(c0, c2);
    float2 mc3 = make_float2(c3.y, -c3.x);
    y[2] = cadd(c1, mc3); y[6] = csub(c1, mc3);
    b1 = make_float2(S * (b1.x + b1.y), S * (b1.y - b1.x));
    b2 = make_float2(b2.y, -b2.x);
    b3 = make_float2(S * (b3.y - b3.x), -S * (b3.x + b3.y));
    float2 d0 = cadd(b0, b2), d1 = csub(b0, b2);
    float2 d2 = cadd(b1, b3), d3 = csub(b1, b3);
    y[1] = cadd(d0, d2); y[5] = csub(d0, d2);
    float2 md3 = make_float2(d3.y, -d3.x);
    y[3] = cadd(d1, md3); y[7] = csub(d1, md3);
}

template <int LS>
__device__ __forceinline__ void pass8(const float2* __restrict__ in,
                                      float2* __restrict__ out, int t) {
    int i = t;
    int j = i & (LS - 1);
    int base = ((i & ~(LS - 1)) << 3) | j;
    float2 v[8], y[8];
#pragma unroll
    for (int q = 0; q < 8; q++) v[q] = in[PADI(i + q * 1024)];
    if (LS > 1) {
#pragma unroll
        for (int q = 1; q < 8; q++)
            v[q] = cmul(v[q], d_tw[j * q * (1024 / LS)]);
    }
    dft8(v, y);
#pragma unroll
    for (int q = 0; q < 8; q++) out[PADI(base + q * LS)] = y[q];
}

__device__ __forceinline__ void fft_passes(float2* A, float2* B, int t) {
    pass8<1>(A, B, t);   __syncthreads();
    pass8<8>(B, A, t);   __syncthreads();
    pass8<64>(A, B, t);  __syncthreads();
    pass8<512>(B, A, t); __syncthreads();
#pragma unroll
    for (int u = 0; u < 4; u++) {
        int i = t + u * 1024;
        float2 a = A[PADI(i)];
        float2 b = cmul(A[PADI(i + 4096)], d_tw[i]);
        B[PADI(i)]        = cadd(a, b);
        B[PADI(i + 4096)] = csub(a, b);
    }
    __syncthreads();
}

// ---------------- forward FFTs: G rows (blocks 0..31) + x rows (32..159) --------
__global__ void __launch_bounds__(1024, 1)
k_fft_fwd(const float* __restrict__ x) {
    extern __shared__ float2 sm[];
    float2* A = sm;
    float2* B = sm + SBUF;
    int t = threadIdx.x;
    const float* ra;
    float2* oa;
    if (blockIdx.x < HIDN / 2) {
        ra = d_h2t + (size_t)(2 * blockIdx.x) * TN;
        oa = d_G   + (size_t)(2 * blockIdx.x) * FSTR;
    } else {
        int bb = blockIdx.x - HIDN / 2;
        ra = x    + (size_t)(2 * bb) * TN;
        oa = d_Xf + (size_t)(2 * bb) * FSTR;
    }
    const float* rb = ra + TN;
#pragma unroll
    for (int u = 0; u < 8; u++) {
        int idx = t + u * 1024;
        A[PADI(idx)] = make_float2(ra[idx], rb[idx]);
    }
    __syncthreads();
    fft_passes(A, B, t);
#pragma unroll
    for (int u = 0; u < 4; u++) {
        int f = t + u * 1024;
        float2 uu = B[PADI(f)];
        float2 vv = B[PADI((TN - f) & (TN - 1))];
        float vx = vv.x, vy = -vv.y;
        oa[f] = make_float2(0.5f * (uu.x + vx), 0.5f * (uu.y + vy));
        float wx = uu.x - vx, wyv = uu.y - vy;
        oa[FSTR + f] = make_float2(0.5f * wyv, -0.5f * wx);
    }
    if (t == 0) {
        float2 uu = B[PADI(TN / 2)];
        oa[TN / 2]        = make_float2(uu.x, 0.f);
        oa[FSTR + TN / 2] = make_float2(uu.y, 0.f);
    }
}

// ---------------- fused filter-GEMM + contraction (512 threads) -----------------
// Per block: 8 freqs, grid 513. Smem: Ms[1024][9] f2 (73728) + Gs dup u64 (8192)
// + Xs[32 i][66] f2 (16896) = 98816 -> 2 blocks/SM = 32 warps.
// Phase1: thread = 8c x 2f; w3 loaded as ulonglong2 (native packed c-pairs).
// Phase2: thread = 1o x 2b x 2f.
#define MROWSTR 9
#define FUSED_SM (73728 + 8192 + 16896)

__global__ void __launch_bounds__(512, 2)
k_fused(const float* __restrict__ w3, const float* __restrict__ b3) {
    extern __shared__ __align__(16) char smraw[];
    float2* Ms = (float2*)smraw;                 // [1024][MROWSTR]
    u64*    Gs = (u64*)(smraw + 73728);          // [64 j][8 f][2] dup'd {g,g}
    float2* Xs = (float2*)(smraw + 73728 + 8192);// [32 i][66], idx = i*66 + b*8 + f
    int f0 = blockIdx.x * 8;
    int nf = NFREQ - f0; if (nf > 8) nf = 8;
    int tid = threadIdx.x;

    // ---- stage G (duplicated u64 pairs) ----
    for (int m = tid; m < HIDN * 8; m += 512) {
        int j = m >> 3, f = m & 7;
        float2 g = (f < nf) ? d_G[(size_t)j * FSTR + f0 + f] : make_float2(0.f, 0.f);
        u64 gx, gy;
        asm("mov.b64 %0, {%1, %1};" : "=l"(gx) : "f"(g.x));
        asm("mov.b64 %0, {%1, %1};" : "=l"(gy) : "f"(g.y));
        Gs[m * 2 + 0] = gx;
        Gs[m * 2 + 1] = gy;
    }
    // ---- stage X: two threads per row (b*32+i), 4 f2 each ----
    {
        int r = tid >> 1, half = tid & 1;
        int b = r >> 5, i = r & 31;
        const float2* xr = d_Xf + (size_t)r * FSTR + f0 + half * 4;
        float2* xd = Xs + i * 66 + b * 8 + half * 4;
        if (nf == 8) {
            const float4* s4 = (const float4*)xr;
            float4* d4 = (float4*)xd;
            d4[0] = s4[0];
            d4[1] = s4[1];
        } else {
#pragma unroll
            for (int f = 0; f < 4; f++) {
                int fg = half * 4 + f;
                xd[f] = (fg < nf) ? xr[f] : make_float2(0.f, 0.f);
            }
        }
    }
    __syncthreads();

    // ---- phase 1: thread = 8c x 2f ----
    {
        int tm = tid >> 2;          // 0..127 : c-block of 8 (c0 = tm*8)
        int tf = tid & 3;           // 0..3   : f-pair (f = 2tf, 2tf+1)
        const char* wp = (const char*)(w3 + tm * 8);
        const u64* gbase = Gs + tf * 4;
        u64 accR[4][2], accI[4][2];
#pragma unroll
        for (int p = 0; p < 4; p++) {
            accR[p][0] = accR[p][1] = 0ull;
            accI[p][0] = accI[p][1] = 0ull;
        }
#pragma unroll 2
        for (int j = 0; j < 64; j++) {
            ulonglong2 wA = *(const ulonglong2*)(wp + (size_t)j * 4096);
            ulonglong2 wB = *(const ulonglong2*)(wp + (size_t)j * 4096 + 16);
            ulonglong2 g0 = *(const ulonglong2*)(gbase + j * 16);      // {gx0,gy0}
            ulonglong2 g1 = *(const ulonglong2*)(gbase + j * 16 + 2);  // {gx1,gy1}
            u64 w[4] = {wA.x, wA.y, wB.x, wB.y};
#pragma unroll
            for (int p = 0; p < 4; p++) {
                asm("fma.rn.f32x2 %0, %1, %2, %0;" : "+l"(accR[p][0]) : "l"(w[p]), "l"(g0.x));
                asm("fma.rn.f32x2 %0, %1, %2, %0;" : "+l"(accI[p][0]) : "l"(w[p]), "l"(g0.y));
                asm("fma.rn.f32x2 %0, %1, %2, %0;" : "+l"(accR[p][1]) : "l"(w[p]), "l"(g1.x));
                asm("fma.rn.f32x2 %0, %1, %2, %0;" : "+l"(accI[p][1]) : "l"(w[p]), "l"(g1.y));
            }
        }
        // handoff: write Ms with XOR-swizzled rows
#pragma unroll
        for (int p = 0; p < 4; p++) {
#pragma unroll
            for (int s = 0; s < 2; s++) {
                float r0, r1, i0, i1;
                asm("mov.b64 {%0, %1}, %2;" : "=f"(r0), "=f"(r1) : "l"(accR[p][s]));
                asm("mov.b64 {%0, %1}, %2;" : "=f"(i0), "=f"(i1) : "l"(accI[p][s]));
                int c0p = tm * 8 + 2 * p;
                if (f0 == 0 && tf == 0 && s == 0) {
                    r0 += (float)TN * b3[c0p];
                    r1 += (float)TN * b3[c0p + 1];
                }
                int o0 = c0p >> 5, ii0 = c0p & 31;
                int f = 2 * tf + s;
                Ms[(o0 * 32 + (ii0 ^ o0)) * MROWSTR + f]       = make_float2(r0, i0);
                Ms[(o0 * 32 + ((ii0 + 1) ^ o0)) * MROWSTR + f] = make_float2(r1, i1);
            }
        }
    }
    __syncthreads();

    // ---- phase 2: thread = 1o x 2b x 2f ----
    {
        int o   = tid >> 4;         // 0..31
        int tb  = (tid >> 2) & 3;   // 0..3 -> b = 2tb+bs
        int tf2 = tid & 3;          // 0..3 -> f = 2tf2+fs
        float2 acc[2][2];           // [bs][fs]
#pragma unroll
        for (int bq = 0; bq < 2; bq++)
#pragma unroll
            for (int fq = 0; fq < 2; fq++) acc[bq][fq] = make_float2(0.f, 0.f);

#pragma unroll 2
        for (int i = 0; i < CINN; i++) {
            float4 xv0 = *(const float4*)(Xs + i * 66 + (2 * tb) * 8 + 2 * tf2);
            float4 xv1 = *(const float4*)(Xs + i * 66 + (2 * tb + 1) * 8 + 2 * tf2);
            const float2* mp = Ms + (o * 32 + (i ^ o)) * MROWSTR + 2 * tf2;
            float2 m0 = mp[0];
            float2 m1 = mp[1];
            acc[0][0].x += xv0.x * m0.x - xv0.y * m0.y;
            acc[0][0].y += xv0.x * m0.y + xv0.y * m0.x;
            acc[0][1].x += xv0.z * m1.x - xv0.w * m1.y;
            acc[0][1].y += xv0.z * m1.y + xv0.w * m1.x;
            acc[1][0].x += xv1.x * m0.x - xv1.y * m0.y;
            acc[1][0].y += xv1.x * m0.y + xv1.y * m0.x;
            acc[1][1].x += xv1.z * m1.x - xv1.w * m1.y;
            acc[1][1].y += xv1.z * m1.y + xv1.w * m1.x;
        }
#pragma unroll
        for (int bs = 0; bs < 2; bs++) {
            int b = 2 * tb + bs;
            float2* yr = d_Yf + (size_t)(b * COUTN + o) * FSTR + f0 + 2 * tf2;
#pragma unroll
            for (int fs = 0; fs < 2; fs++)
                if (2 * tf2 + fs < nf) yr[fs] = acc[bs][fs];
        }
    }
}

// ---------------- packed inverse FFT via conj(forward(conj)) --------------------
__global__ void __launch_bounds__(1024, 1)
k_fft_inv(float* __restrict__ out, const float* __restrict__ bias) {
    extern __shared__ float2 sm[];
    float2* A = sm;
    float2* B = sm + SBUF;
    int t = threadIdx.x;
    int b = blockIdx.x >> 4, q = blockIdx.x & 15;
    int oc = 2 * q;
    const float2* ra = d_Yf + (size_t)(b * COUTN + oc) * FSTR;
    const float2* rb = ra + FSTR;
#pragma unroll
    for (int u = 0; u < 4; u++) {
        int f = t + u * 1024;
        float2 Ya = ra[f], Yb = rb[f];
        A[PADI(f)] = make_float2(Ya.x - Yb.y, -(Ya.y + Yb.x));
        if (f > 0)
            A[PADI(TN - f)] = make_float2(Ya.x + Yb.y, Ya.y - Yb.x);
    }
    if (t == 0) {
        float2 Ya = ra[TN / 2], Yb = rb[TN / 2];
        A[PADI(TN / 2)] = make_float2(Ya.x - Yb.y, -(Ya.y + Yb.x));
    }
    __syncthreads();
    fft_passes(A, B, t);
    const float sc = 1.0f / (float)TN;
    float ba = bias[oc], bb = bias[oc + 1];
    float* pa = out + (size_t)(b * COUTN + oc) * TN;
    float* pb = pa + TN;
#pragma unroll
    for (int u = 0; u < 8; u++) {
        int i = t + u * 1024;
        float2 v = B[PADI(i)];
        pa[i] =  v.x * sc + ba;
        pb[i] = -v.y * sc + bb;
    }
}

// ---------------- launch --------------------------------------------------------
extern "C" void kernel_launch(void* const* d_in, const int* in_sizes, int n_in,
                              void* d_out, int out_size) {
    const float* x    = (const float*)d_in[0];
    const float* w1   = (const float*)d_in[1];
    const float* b1   = (const float*)d_in[2];
    const float* w2   = (const float*)d_in[3];
    const float* b2   = (const float*)d_in[4];
    const float* w3   = (const float*)d_in[5];
    const float* b3   = (const float*)d_in[6];
    const float* bias = (const float*)d_in[7];
    float* out = (float*)d_out;

    const int fftSm = 2 * SBUF * (int)sizeof(float2);   // 139264

    cudaFuncSetAttribute(k_fft_fwd, cudaFuncAttributeMaxDynamicSharedMemorySize, fftSm);
    cudaFuncSetAttribute(k_fft_inv, cudaFuncAttributeMaxDynamicSharedMemorySize, fftSm);
    cudaFuncSetAttribute(k_fused,   cudaFuncAttributeMaxDynamicSharedMemorySize, FUSED_SM);

    k_twiddle<<<32, 256>>>();
    k_mlp<<<TN / 4, 256>>>(w1, b1, w2, b2);
    k_fft_fwd<<<HIDN / 2 + BN * CINN / 2, 1024, fftSm>>>(x);
    k_fused<<<(NFREQ + 7) / 8, 512, FUSED_SM>>>(w3, b3);
    k_fft_inv<<<BN * COUTN / 2, 1024, fftSm>>>(out, bias);
}

// round 17
// speedup vs baseline: 1.9265x; 1.1527x over previous
#include <cuda_runtime.h>
#include <math.h>

// Problem constants
#define TN    8192
#define LOGN  13
#define HIDN  64
#define BN    8
#define CINN  32
#define COUTN 32
#define CTOTN 1024   // COUT*CIN
#define NFREQ 4097   // rfft bins
#define FSTR  4104   // padded row stride (complex), mult of 8

// padded smem index: one float2 of pad every 16 (conflict-free phases)
#define PADI(i) ((i) + ((i) >> 4))
#define SBUF 8704

typedef unsigned long long u64;

// ---------------- device scratch ------------------------------------------------
__device__ float2 d_tw[TN];                        // exp(-2*pi*i*k/N)
__device__ float  d_h2t[HIDN * TN];                // h2 transposed: [j][t]
__device__ float2 d_G[HIDN * FSTR];                // rfft(h2)
__device__ float2 d_Xf[(size_t)(BN * CINN) * FSTR];   // rfft(x)
__device__ float2 d_Yf[(size_t)(BN * COUTN) * FSTR];  // result spectra (half)

// ---------------- complex helpers -----------------------------------------------
__device__ __forceinline__ float2 cadd(float2 a, float2 b) { return make_float2(a.x + b.x, a.y + b.y); }
__device__ __forceinline__ float2 csub(float2 a, float2 b) { return make_float2(a.x - b.x, a.y - b.y); }
__device__ __forceinline__ float2 cmul(float2 a, float2 b) {
    return make_float2(a.x * b.x - a.y * b.y, a.x * b.y + a.y * b.x);
}

// ---------------- twiddle table -------------------------------------------------
__global__ void k_twiddle() {
    int k = blockIdx.x * blockDim.x + threadIdx.x;
    if (k < TN) {
        float s, c;
        sincospif(-2.0f * (float)k / (float)TN, &s, &c);
        d_tw[k] = make_float2(c, s);
    }
}

// ---------------- MLP -----------------------------------------------------------
__global__ void k_mlp(const float* __restrict__ w1, const float* __restrict__ b1,
                      const float* __restrict__ w2, const float* __restrict__ b2) {
    __shared__ float h1[4][HIDN];
    int g = threadIdx.x >> 6;
    int j = threadIdx.x & 63;
    int t = blockIdx.x * 4 + g;
    float pos = (float)t * (1.0f / (float)(TN - 1));
    float z = pos * w1[j] + b1[j];
    h1[g][j] = 0.5f * z * (1.0f + erff(z * 0.7071067811865476f));
    __syncthreads();
    float acc = b2[j];
#pragma unroll
    for (int k = 0; k < HIDN; k++) acc += h1[g][k] * w2[k * HIDN + j];
    float h2 = 0.5f * acc * (1.0f + erff(acc * 0.7071067811865476f));
    d_h2t[j * TN + t] = h2;
}

// ---------------- radix-8 Stockham FFT (8192 pts, 1024 threads, ping-pong) ------
__device__ __forceinline__ void dft8(const float2* v, float2* y) {
    const float S = 0.70710678118654752f;
    float2 a0 = cadd(v[0], v[4]), b0 = csub(v[0], v[4]);
    float2 a1 = cadd(v[1], v[5]), b1 = csub(v[1], v[5]);
    float2 a2 = cadd(v[2], v[6]), b2 = csub(v[2], v[6]);
    float2 a3 = cadd(v[3], v[7]), b3 = csub(v[3], v[7]);
    float2 c0 = cadd(a0, a2), c1 = csub(a0, a2);
    float2 c2 = cadd(a1, a3), c3 = csub(a1, a3);
    y[0] = cadd(c0, c2); y[4] = csub(c0, c2);
    float2 mc3 = make_float2(c3.y, -c3.x);
    y[2] = cadd(c1, mc3); y[6] = csub(c1, mc3);
    b1 = make_float2(S * (b1.x + b1.y), S * (b1.y - b1.x));
    b2 = make_float2(b2.y, -b2.x);
    b3 = make_float2(S * (b3.y - b3.x), -S * (b3.x + b3.y));
    float2 d0 = cadd(b0, b2), d1 = csub(b0, b2);
    float2 d2 = cadd(b1, b3), d3 = csub(b1, b3);
    y[1] = cadd(d0, d2); y[5] = csub(d0, d2);
    float2 md3 = make_float2(d3.y, -d3.x);
    y[3] = cadd(d1, md3); y[7] = csub(d1, md3);
}

template <int LS>
__device__ __forceinline__ void pass8(const float2* __restrict__ in,
                                      float2* __restrict__ out, int t) {
    int i = t;
    int j = i & (LS - 1);
    int base = ((i & ~(LS - 1)) << 3) | j;
    float2 v[8], y[8];
#pragma unroll
    for (int q = 0; q < 8; q++) v[q] = in[PADI(i + q * 1024)];
    if (LS > 1) {
#pragma unroll
        for (int q = 1; q < 8; q++)
            v[q] = cmul(v[q], d_tw[j * q * (1024 / LS)]);
    }
    dft8(v, y);
#pragma unroll
    for (int q = 0; q < 8; q++) out[PADI(base + q * LS)] = y[q];
}

__device__ __forceinline__ void fft_passes(float2* A, float2* B, int t) {
    pass8<1>(A, B, t);   __syncthreads();
    pass8<8>(B, A, t);   __syncthreads();
    pass8<64>(A, B, t);  __syncthreads();
    pass8<512>(B, A, t); __syncthreads();
#pragma unroll
    for (int u = 0; u < 4; u++) {
        int i = t + u * 1024;
        float2 a = A[PADI(i)];
        float2 b = cmul(A[PADI(i + 4096)], d_tw[i]);
        B[PADI(i)]        = cadd(a, b);
        B[PADI(i + 4096)] = csub(a, b);
    }
    __syncthreads();
}

// ---------------- forward FFTs: G rows (blocks 0..31) + x rows (32..159) --------
__global__ void __launch_bounds__(1024, 1)
k_fft_fwd(const float* __restrict__ x) {
    extern __shared__ float2 sm[];
    float2* A = sm;
    float2* B = sm + SBUF;
    int t = threadIdx.x;
    const float* ra;
    float2* oa;
    if (blockIdx.x < HIDN / 2) {
        ra = d_h2t + (size_t)(2 * blockIdx.x) * TN;
        oa = d_G   + (size_t)(2 * blockIdx.x) * FSTR;
    } else {
        int bb = blockIdx.x - HIDN / 2;
        ra = x    + (size_t)(2 * bb) * TN;
        oa = d_Xf + (size_t)(2 * bb) * FSTR;
    }
    const float* rb = ra + TN;
#pragma unroll
    for (int u = 0; u < 8; u++) {
        int idx = t + u * 1024;
        A[PADI(idx)] = make_float2(ra[idx], rb[idx]);
    }
    __syncthreads();
    fft_passes(A, B, t);
#pragma unroll
    for (int u = 0; u < 4; u++) {
        int f = t + u * 1024;
        float2 uu = B[PADI(f)];
        float2 vv = B[PADI((TN - f) & (TN - 1))];
        float vx = vv.x, vy = -vv.y;
        oa[f] = make_float2(0.5f * (uu.x + vx), 0.5f * (uu.y + vy));
        float wx = uu.x - vx, wyv = uu.y - vy;
        oa[FSTR + f] = make_float2(0.5f * wyv, -0.5f * wx);
    }
    if (t == 0) {
        float2 uu = B[PADI(TN / 2)];
        oa[TN / 2]        = make_float2(uu.x, 0.f);
        oa[FSTR + TN / 2] = make_float2(uu.y, 0.f);
    }
}

// ---------------- fused filter-GEMM + contraction (256 thr, broadcast-G) --------
// Per block: 8 freqs, grid 513.
// Phase1: thread = 4c x 8f. w3 read once per block (coalesced LDG.128/thread/j);
//         G read via warp-uniform LDS.128 broadcast. FMA-bound by design.
// Phase2: thread = 2o x 2b x 2f (R6-measured shape).
// Smem: Ms[1024][9] f2 (73728) + Gs dup u64 (8192) + Xs[32][66] f2 (16896).
#define MROWSTR 9
#define FUSED_SM (73728 + 8192 + 16896)

__global__ void __launch_bounds__(256, 2)
k_fused(const float* __restrict__ w3, const float* __restrict__ b3) {
    extern __shared__ __align__(16) char smraw[];
    float2* Ms = (float2*)smraw;                 // [1024][MROWSTR]
    u64*    Gs = (u64*)(smraw + 73728);          // [64 j][8 f][2] dup'd {g,g}
    float2* Xs = (float2*)(smraw + 73728 + 8192);// [32 i][66], idx = i*66 + b*8 + f
    int f0 = blockIdx.x * 8;
    int nf = NFREQ - f0; if (nf > 8) nf = 8;
    int tid = threadIdx.x;

    // ---- stage G (duplicated u64 pairs) ----
    for (int m = tid; m < HIDN * 8; m += 256) {
        int j = m >> 3, f = m & 7;
        float2 g = (f < nf) ? d_G[(size_t)j * FSTR + f0 + f] : make_float2(0.f, 0.f);
        u64 gx, gy;
        asm("mov.b64 %0, {%1, %1};" : "=l"(gx) : "f"(g.x));
        asm("mov.b64 %0, {%1, %1};" : "=l"(gy) : "f"(g.y));
        Gs[m * 2 + 0] = gx;
        Gs[m * 2 + 1] = gy;
    }
    // ---- stage X: one row (b*32+i) per thread, 8 complex = 4 float4 ----
    {
        int b = tid >> 5, i = tid & 31;
        const float2* xr = d_Xf + (size_t)tid * FSTR + f0;
        float2* xd = Xs + i * 66 + b * 8;
        if (nf == 8) {
            const float4* s4 = (const float4*)xr;
            float4* d4 = (float4*)xd;
#pragma unroll
            for (int q = 0; q < 4; q++) d4[q] = s4[q];
        } else {
#pragma unroll
            for (int f = 0; f < 8; f++)
                xd[f] = (f < nf) ? xr[f] : make_float2(0.f, 0.f);
        }
    }
    __syncthreads();

    // ---- phase 1: thread = 4c x 8f (c = tid*4 .. +3) ----
    {
        const char* wp = (const char*)(w3 + tid * 4);
        u64 accR[2][8], accI[2][8];
#pragma unroll
        for (int p = 0; p < 2; p++)
#pragma unroll
            for (int f = 0; f < 8; f++) { accR[p][f] = 0ull; accI[p][f] = 0ull; }

#pragma unroll 2
        for (int j = 0; j < 64; j++) {
            ulonglong2 wv = *(const ulonglong2*)(wp + (size_t)j * 4096); // {c01, c23}
            const u64* gj = Gs + j * 16;
#pragma unroll
            for (int f = 0; f < 8; f++) {
                ulonglong2 g = *(const ulonglong2*)(gj + f * 2);   // {gx, gy} broadcast
                asm("fma.rn.f32x2 %0, %1, %2, %0;" : "+l"(accR[0][f]) : "l"(wv.x), "l"(g.x));
                asm("fma.rn.f32x2 %0, %1, %2, %0;" : "+l"(accI[0][f]) : "l"(wv.x), "l"(g.y));
                asm("fma.rn.f32x2 %0, %1, %2, %0;" : "+l"(accR[1][f]) : "l"(wv.y), "l"(g.x));
                asm("fma.rn.f32x2 %0, %1, %2, %0;" : "+l"(accI[1][f]) : "l"(wv.y), "l"(g.y));
            }
        }
        // handoff: unpack, write Ms with XOR-swizzled rows
#pragma unroll
        for (int p = 0; p < 2; p++) {
            int c0p = tid * 4 + 2 * p;
            float b30 = 0.f, b31 = 0.f;
            if (f0 == 0) { b30 = (float)TN * b3[c0p]; b31 = (float)TN * b3[c0p + 1]; }
            int o0  = c0p >> 5, ii0 = c0p & 31;
            float2* row0 = Ms + (o0 * 32 + (ii0 ^ o0)) * MROWSTR;
            float2* row1 = Ms + (o0 * 32 + ((ii0 + 1) ^ o0)) * MROWSTR;
#pragma unroll
            for (int f = 0; f < 8; f++) {
                float r0, r1, i0, i1;
                asm("mov.b64 {%0, %1}, %2;" : "=f"(r0), "=f"(r1) : "l"(accR[p][f]));
                asm("mov.b64 {%0, %1}, %2;" : "=f"(i0), "=f"(i1) : "l"(accI[p][f]));
                if (f == 0) { r0 += b30; r1 += b31; }
                row0[f] = make_float2(r0, i0);
                row1[f] = make_float2(r1, i1);
            }
        }
    }
    __syncthreads();

    // ---- phase 2: thread = 2o x 2b x 2f ----
    {
        int to  = tid >> 4;         // 0..15 -> o = 2to+os
        int tb  = (tid >> 2) & 3;   // 0..3  -> b = 2tb+bs
        int tf2 = tid & 3;          // 0..3  -> f = 2tf2+fs
        float2 acc[2][2][2];        // [os][bs][fs]
#pragma unroll
        for (int a = 0; a < 2; a++)
#pragma unroll
            for (int bq = 0; bq < 2; bq++)
#pragma unroll
                for (int fq = 0; fq < 2; fq++) acc[a][bq][fq] = make_float2(0.f, 0.f);

#pragma unroll 2
        for (int i = 0; i < CINN; i++) {
            float4 xv0 = *(const float4*)(Xs + i * 66 + (2 * tb) * 8 + 2 * tf2);
            float4 xv1 = *(const float4*)(Xs + i * 66 + (2 * tb + 1) * 8 + 2 * tf2);
            float2 m0[2], m1[2];
#pragma unroll
            for (int os = 0; os < 2; os++) {
                int o = 2 * to + os;
                const float2* mp = Ms + (o * 32 + (i ^ o)) * MROWSTR + 2 * tf2;
                m0[os] = mp[0];
                m1[os] = mp[1];
            }
#pragma unroll
            for (int os = 0; os < 2; os++) {
                acc[os][0][0].x += xv0.x * m0[os].x - xv0.y * m0[os].y;
                acc[os][0][0].y += xv0.x * m0[os].y + xv0.y * m0[os].x;
                acc[os][0][1].x += xv0.z * m1[os].x - xv0.w * m1[os].y;
                acc[os][0][1].y += xv0.z * m1[os].y + xv0.w * m1[os].x;
                acc[os][1][0].x += xv1.x * m0[os].x - xv1.y * m0[os].y;
                acc[os][1][0].y += xv1.x * m0[os].y + xv1.y * m0[os].x;
                acc[os][1][1].x += xv1.z * m1[os].x - xv1.w * m1[os].y;
                acc[os][1][1].y += xv1.z * m1[os].y + xv1.w * m1[os].x;
            }
        }
#pragma unroll
        for (int os = 0; os < 2; os++)
#pragma unroll
            for (int bs = 0; bs < 2; bs++) {
                int o = 2 * to + os, b = 2 * tb + bs;
                float2* yr = d_Yf + (size_t)(b * COUTN + o) * FSTR + f0 + 2 * tf2;
#pragma unroll
                for (int fs = 0; fs < 2; fs++)
                    if (2 * tf2 + fs < nf) yr[fs] = acc[os][bs][fs];
            }
    }
}

// ---------------- packed inverse FFT via conj(forward(conj)) --------------------
__global__ void __launch_bounds__(1024, 1)
k_fft_inv(float* __restrict__ out, const float* __restrict__ bias) {
    extern __shared__ float2 sm[];
    float2* A = sm;
    float2* B = sm + SBUF;
    int t = threadIdx.x;
    int b = blockIdx.x >> 4, q = blockIdx.x & 15;
    int oc = 2 * q;
    const float2* ra = d_Yf + (size_t)(b * COUTN + oc) * FSTR;
    const float2* rb = ra + FSTR;
#pragma unroll
    for (int u = 0; u < 4; u++) {
        int f = t + u * 1024;
        float2 Ya = ra[f], Yb = rb[f];
        A[PADI(f)] = make_float2(Ya.x - Yb.y, -(Ya.y + Yb.x));
        if (f > 0)
            A[PADI(TN - f)] = make_float2(Ya.x + Yb.y, Ya.y - Yb.x);
    }
    if (t == 0) {
        float2 Ya = ra[TN / 2], Yb = rb[TN / 2];
        A[PADI(TN / 2)] = make_float2(Ya.x - Yb.y, -(Ya.y + Yb.x));
    }
    __syncthreads();
    fft_passes(A, B, t);
    const float sc = 1.0f / (float)TN;
    float ba = bias[oc], bb = bias[oc + 1];
    float* pa = out + (size_t)(b * COUTN + oc) * TN;
    float* pb = pa + TN;
#pragma unroll
    for (int u = 0; u < 8; u++) {
        int i = t + u * 1024;
        float2 v = B[PADI(i)];
        pa[i] =  v.x * sc + ba;
        pb[i] = -v.y * sc + bb;
    }
}

// ---------------- launch --------------------------------------------------------
extern "C" void kernel_launch(void* const* d_in, const int* in_sizes, int n_in,
                              void* d_out, int out_size) {
    const float* x    = (const float*)d_in[0];
    const float* w1   = (const float*)d_in[1];
    const float* b1   = (const float*)d_in[2];
    const float* w2   = (const float*)d_in[3];
    const float* b2   = (const float*)d_in[4];
    const float* w3   = (const float*)d_in[5];
    const float* b3   = (const float*)d_in[6];
    const float* bias = (const float*)d_in[7];
    float* out = (float*)d_out;

    const int fftSm = 2 * SBUF * (int)sizeof(float2);   // 139264

    cudaFuncSetAttribute(k_fft_fwd, cudaFuncAttributeMaxDynamicSharedMemorySize, fftSm);
    cudaFuncSetAttribute(k_fft_inv, cudaFuncAttributeMaxDynamicSharedMemorySize, fftSm);
    cudaFuncSetAttribute(k_fused,   cudaFuncAttributeMaxDynamicSharedMemorySize, FUSED_SM);

    k_twiddle<<<32, 256>>>();
    k_mlp<<<TN / 4, 256>>>(w1, b1, w2, b2);
    k_fft_fwd<<<HIDN / 2 + BN * CINN / 2, 1024, fftSm>>>(x);
    k_fused<<<(NFREQ + 7) / 8, 256, FUSED_SM>>>(w3, b3);
    k_fft_inv<<<BN * COUTN / 2, 1024, fftSm>>>(out, bias);
}